// round 2
// baseline (speedup 1.0000x reference)
#include <cuda_runtime.h>
#include <cstdint>

#define NS 64      // samples per block
#define NT 256     // threads per block
#define FPAD 66    // padded row stride (floats) for featT / f1T / f2T

// SMEM float offsets
#define OFF_WBUF 0                       // 24576 floats: fc1 weight dbl-buf; also signal tile (9600) & fc2 wbuf (8192)
#define OFF_FEAT 24576                   // 23760 floats: featT[360][66] -> f1T[256][66] -> f2T[64][66]
#define OFF_SMALL (24576 + 23760)        // small consts (1310 floats)
#define SM_FLOATS (OFF_SMALL + 1312)
#define SMBYTES (SM_FLOATS * 4)

// small-const layout within OFF_SMALL
#define SW1 0      // conv1_w 45
#define SB1 45     // conv1_b 5
#define SW2 50     // conv2_w 150
#define SB2 200    // conv2_b 10
#define SFB1 210   // fc1_b 256
#define SFB2 466   // fc2_b 64
#define SPW 530    // pamap_w 768
#define SPB 1298   // pamap_b 12

__device__ __forceinline__ unsigned long long pack2(float x, float y) {
    unsigned long long v;
    asm("mov.b64 %0, {%1, %2};" : "=l"(v) : "f"(x), "f"(y));
    return v;
}
__device__ __forceinline__ float2 unpk(unsigned long long v) {
    float2 r;
    asm("mov.b64 {%0, %1}, %2;" : "=f"(r.x), "=f"(r.y) : "l"(v));
    return r;
}
// d = a * b + d  (packed 2x fp32, Blackwell FFMA2)
__device__ __forceinline__ void fma2(unsigned long long& d, unsigned long long a, unsigned long long b) {
    asm("fma.rn.f32x2 %0, %1, %2, %0;" : "+l"(d) : "l"(a), "l"(b));
}
// 8-byte shared load into packed register pair
__device__ __forceinline__ unsigned long long ld2s(const float* p) {
    unsigned long long v;
    unsigned a = (unsigned)__cvta_generic_to_shared(p);
    asm volatile("ld.shared.b64 %0, [%1];" : "=l"(v) : "r"(a));
    return v;
}

// stage fc1 weight chunk (24 k's, all 256 outputs, duplicated (w,w)) into buffer
__device__ __forceinline__ void fc1_store(float* sm, const float4* pf, int tid, int buf) {
    float2* wb = (float2*)(sm + OFF_WBUF) + buf * (24 * 256);
    const int j8 = tid >> 5, nn = tid & 31;   // output o = tid = j8*32+nn
#pragma unroll
    for (int i = 0; i < 6; ++i) {
        const int kk = i * 4;
        wb[((kk + 0) * 8 + j8) * 32 + nn] = make_float2(pf[i].x, pf[i].x);
        wb[((kk + 1) * 8 + j8) * 32 + nn] = make_float2(pf[i].y, pf[i].y);
        wb[((kk + 2) * 8 + j8) * 32 + nn] = make_float2(pf[i].z, pf[i].z);
        wb[((kk + 3) * 8 + j8) * 32 + nn] = make_float2(pf[i].w, pf[i].w);
    }
}

// stage fc2 weight chunk (32 k's, 64 outputs, duplicated)
__device__ __forceinline__ void fc2_store(float* sm, const float4* pf, int tid, int buf) {
    float2* wb = (float2*)(sm + OFF_WBUF) + buf * (32 * 64);
    const int o = tid & 63, kq = tid >> 6;
    const int j = o >> 5, nn = o & 31;
#pragma unroll
    for (int i = 0; i < 2; ++i) {
        const int kk = kq * 8 + i * 4;
        wb[((kk + 0) * 2 + j) * 32 + nn] = make_float2(pf[i].x, pf[i].x);
        wb[((kk + 1) * 2 + j) * 32 + nn] = make_float2(pf[i].y, pf[i].y);
        wb[((kk + 2) * 2 + j) * 32 + nn] = make_float2(pf[i].z, pf[i].z);
        wb[((kk + 3) * 2 + j) * 32 + nn] = make_float2(pf[i].w, pf[i].w);
    }
}

__global__ __launch_bounds__(NT, 1)
void convnet_fused_kernel(const float* __restrict__ sig,
                          const float* __restrict__ w1, const float* __restrict__ b1,
                          const float* __restrict__ w2, const float* __restrict__ b2,
                          const float* __restrict__ fw1, const float* __restrict__ fb1,
                          const float* __restrict__ fw2, const float* __restrict__ fb2,
                          const float* __restrict__ pw, const float* __restrict__ pb,
                          float* __restrict__ out)
{
    extern __shared__ float sm[];
    const int tid = threadIdx.x;
    const int bx  = blockIdx.x;
    const int ng = tid & 31;   // output group lane
    const int mg = tid >> 5;   // sample group (8 samples each)

    // ---- stage small constants ----
    for (int i = tid; i < 45;  i += NT) sm[OFF_SMALL + SW1 + i] = w1[i];
    if (tid < 5)                         sm[OFF_SMALL + SB1 + tid] = b1[tid];
    for (int i = tid; i < 150; i += NT) sm[OFF_SMALL + SW2 + i] = w2[i];
    if (tid < 10)                        sm[OFF_SMALL + SB2 + tid] = b2[tid];
    sm[OFF_SMALL + SFB1 + tid] = fb1[tid];
    if (tid < 64)                        sm[OFF_SMALL + SFB2 + tid] = fb2[tid];
    for (int i = tid; i < 768; i += NT) sm[OFF_SMALL + SPW + i] = pw[i];
    if (tid < 12)                        sm[OFF_SMALL + SPB + tid] = pb[tid];

    // ---- load signal tile: 64 samples x 150 floats (contiguous) ----
    {
        const float4* g = (const float4*)(sig + (size_t)bx * NS * 150);
        float4* s4 = (float4*)(sm + OFF_WBUF);
        for (int i = tid; i < NS * 150 / 4; i += NT) s4[i] = g[i];
    }
    __syncthreads();

    // ---- featurize: running_std -> conv1 -> conv2 -> featT[k][sample] ----
    {
        const int s  = tid & 63;
        const int t0 = (tid >> 6) * 9;           // 4 threads per sample, 9 t's each
        const float* xs = sm + OFF_WBUF + s * 150;
        float xv[3][23];
#pragma unroll
        for (int j = 0; j < 23; ++j)
#pragma unroll
            for (int c = 0; c < 3; ++c)
                xv[c][j] = xs[(t0 + j) * 3 + c];

        float sd[3][13];
#pragma unroll
        for (int c = 0; c < 3; ++c)
#pragma unroll
            for (int tt = 0; tt < 13; ++tt) {
                float s1 = 0.f, s2 = 0.f;
#pragma unroll
                for (int j = 0; j < 10; ++j) { float v = xv[c][tt + j]; s1 += v; s2 += v * v; }
                float var = (s2 - s1 * s1 * 0.1f) * (1.0f / 9.0f);
                sd[c][tt] = sqrtf(fmaxf(var, 0.f));
            }

        float h1[5][11];
        const float* w1s = sm + OFF_SMALL + SW1;
#pragma unroll
        for (int o = 0; o < 5; ++o) {
            float bb = sm[OFF_SMALL + SB1 + o];
#pragma unroll
            for (int tt = 0; tt < 11; ++tt) h1[o][tt] = bb;
#pragma unroll
            for (int c = 0; c < 3; ++c)
#pragma unroll
                for (int k = 0; k < 3; ++k) {
                    float w = w1s[o * 9 + c * 3 + k];
#pragma unroll
                    for (int tt = 0; tt < 11; ++tt) h1[o][tt] += w * sd[c][tt + k];
                }
#pragma unroll
            for (int tt = 0; tt < 11; ++tt) h1[o][tt] = fmaxf(h1[o][tt], 0.f);
        }

        const float* w2s = sm + OFF_SMALL + SW2;
        float* ftT = sm + OFF_FEAT;
#pragma unroll
        for (int o = 0; o < 10; ++o) {
            float a2[9];
            float bb = sm[OFF_SMALL + SB2 + o];
#pragma unroll
            for (int tt = 0; tt < 9; ++tt) a2[tt] = bb;
#pragma unroll
            for (int i = 0; i < 5; ++i)
#pragma unroll
                for (int k = 0; k < 3; ++k) {
                    float w = w2s[o * 15 + i * 3 + k];
#pragma unroll
                    for (int tt = 0; tt < 9; ++tt) a2[tt] += w * h1[i][tt + k];
                }
#pragma unroll
            for (int tt = 0; tt < 9; ++tt)
                ftT[((t0 + tt) * 10 + o) * FPAD + s] = fmaxf(a2[tt], 0.f);
        }
    }
    __syncthreads();

    // ---- fc1: 360 -> 256, register-blocked GEMM with f32x2 packing ----
    unsigned long long acc[4][8];
#pragma unroll
    for (int j = 0; j < 8; ++j) {
        float b = sm[OFF_SMALL + SFB1 + j * 32 + ng];
        unsigned long long pb2 = pack2(b, b);
#pragma unroll
        for (int p = 0; p < 4; ++p) acc[p][j] = pb2;
    }
    float4 pf[6];
    {
        const float4* g = (const float4*)(fw1 + tid * 360);
#pragma unroll
        for (int i = 0; i < 6; ++i) pf[i] = g[i];
    }
    fc1_store(sm, pf, tid, 0);
    __syncthreads();

#pragma unroll 1
    for (int c = 0; c < 15; ++c) {
        if (c < 14) {
            const float4* g = (const float4*)(fw1 + tid * 360 + (c + 1) * 24);
#pragma unroll
            for (int i = 0; i < 6; ++i) pf[i] = g[i];
        }
        const float2* wb = (const float2*)(sm + OFF_WBUF) + (c & 1) * (24 * 256);
        const float* ft  = sm + OFF_FEAT + c * 24 * FPAD + mg * 8;
#pragma unroll 4
        for (int kk = 0; kk < 24; ++kk) {
            unsigned long long a0 = ld2s(ft + kk * FPAD + 0);
            unsigned long long a1 = ld2s(ft + kk * FPAD + 2);
            unsigned long long a2 = ld2s(ft + kk * FPAD + 4);
            unsigned long long a3 = ld2s(ft + kk * FPAD + 6);
#pragma unroll
            for (int j = 0; j < 8; ++j) {
                unsigned long long bb = ld2s((const float*)(wb + (kk * 8 + j) * 32 + ng));
                fma2(acc[0][j], a0, bb);
                fma2(acc[1][j], a1, bb);
                fma2(acc[2][j], a2, bb);
                fma2(acc[3][j], a3, bb);
            }
        }
        if (c < 14) {
            __syncthreads();
            fc1_store(sm, pf, tid, (c + 1) & 1);
            __syncthreads();
        }
    }

    // ---- relu + redistribute f1 (transposed) ----
    __syncthreads();
    {
        float* f1T = sm + OFF_FEAT;
#pragma unroll
        for (int j = 0; j < 8; ++j) {
            const int o = j * 32 + ng;
#pragma unroll
            for (int p = 0; p < 4; ++p) {
                float2 v = unpk(acc[p][j]);
                v.x = fmaxf(v.x, 0.f); v.y = fmaxf(v.y, 0.f);
                *(float2*)(f1T + o * FPAD + mg * 8 + p * 2) = v;
            }
        }
    }
    __syncthreads();

    // ---- fc2: 256 -> 64 ----
    unsigned long long acc2[4][2];
#pragma unroll
    for (int j = 0; j < 2; ++j) {
        float b = sm[OFF_SMALL + SFB2 + j * 32 + ng];
        unsigned long long pb2 = pack2(b, b);
#pragma unroll
        for (int p = 0; p < 4; ++p) acc2[p][j] = pb2;
    }
    float4 pf2[2];
    {
        const int o = tid & 63, kq = tid >> 6;
        const float4* g = (const float4*)(fw2 + o * 256 + kq * 8);
        pf2[0] = g[0]; pf2[1] = g[1];
    }
    fc2_store(sm, pf2, tid, 0);
    __syncthreads();

#pragma unroll 1
    for (int c = 0; c < 8; ++c) {
        if (c < 7) {
            const int o = tid & 63, kq = tid >> 6;
            const float4* g = (const float4*)(fw2 + o * 256 + (c + 1) * 32 + kq * 8);
            pf2[0] = g[0]; pf2[1] = g[1];
        }
        const float2* wb = (const float2*)(sm + OFF_WBUF) + (c & 1) * (32 * 64);
        const float* ft  = sm + OFF_FEAT + c * 32 * FPAD + mg * 8;
#pragma unroll 8
        for (int kk = 0; kk < 32; ++kk) {
            unsigned long long a0 = ld2s(ft + kk * FPAD + 0);
            unsigned long long a1 = ld2s(ft + kk * FPAD + 2);
            unsigned long long a2 = ld2s(ft + kk * FPAD + 4);
            unsigned long long a3 = ld2s(ft + kk * FPAD + 6);
#pragma unroll
            for (int j = 0; j < 2; ++j) {
                unsigned long long bb = ld2s((const float*)(wb + (kk * 2 + j) * 32 + ng));
                fma2(acc2[0][j], a0, bb);
                fma2(acc2[1][j], a1, bb);
                fma2(acc2[2][j], a2, bb);
                fma2(acc2[3][j], a3, bb);
            }
        }
        if (c < 7) {
            __syncthreads();
            fc2_store(sm, pf2, tid, (c + 1) & 1);
            __syncthreads();
        }
    }

    // ---- relu + redistribute f2 (transposed) ----
    __syncthreads();
    {
        float* f2T = sm + OFF_FEAT;
#pragma unroll
        for (int j = 0; j < 2; ++j) {
            const int o = j * 32 + ng;
#pragma unroll
            for (int p = 0; p < 4; ++p) {
                float2 v = unpk(acc2[p][j]);
                v.x = fmaxf(v.x, 0.f); v.y = fmaxf(v.y, 0.f);
                *(float2*)(f2T + o * FPAD + mg * 8 + p * 2) = v;
            }
        }
    }
    __syncthreads();

    // ---- head (64 -> 12) + log_softmax : one thread per sample ----
    if (tid < 64) {
        const float* f2T = sm + OFF_FEAT;
        const float* pws = sm + OFF_SMALL + SPW;
        float l[12];
#pragma unroll
        for (int j = 0; j < 12; ++j) l[j] = sm[OFF_SMALL + SPB + j];
        for (int k = 0; k < 64; ++k) {
            float v = f2T[k * FPAD + tid];
#pragma unroll
            for (int j = 0; j < 12; ++j) l[j] += v * pws[j * 64 + k];
        }
        float m = l[0];
#pragma unroll
        for (int j = 1; j < 12; ++j) m = fmaxf(m, l[j]);
        float ssum = 0.f;
#pragma unroll
        for (int j = 0; j < 12; ++j) ssum += expf(l[j] - m);
        float lse = m + logf(ssum);
        float* op = out + ((size_t)bx * 64 + tid) * 12;
#pragma unroll
        for (int j = 0; j < 12; ++j) op[j] = l[j] - lse;
    }
}

extern "C" void kernel_launch(void* const* d_in, const int* in_sizes, int n_in,
                              void* d_out, int out_size)
{
    (void)n_in; (void)out_size;
    const float* sig = (const float*)d_in[0];
    const float* w1  = (const float*)d_in[1];
    const float* b1  = (const float*)d_in[2];
    const float* w2  = (const float*)d_in[3];
    const float* b2  = (const float*)d_in[4];
    const float* fw1 = (const float*)d_in[5];
    const float* fb1 = (const float*)d_in[6];
    const float* fw2 = (const float*)d_in[7];
    const float* fb2 = (const float*)d_in[8];
    const float* pw  = (const float*)d_in[9];
    const float* pb  = (const float*)d_in[10];
    float* out = (float*)d_out;

    const int B = in_sizes[0] / 150;        // (B, 50, 3)
    const int nblocks = B / NS;             // 131072 / 64 = 2048

    cudaFuncSetAttribute(convnet_fused_kernel,
                         cudaFuncAttributeMaxDynamicSharedMemorySize, SMBYTES);
    convnet_fused_kernel<<<nblocks, NT, SMBYTES>>>(
        sig, w1, b1, w2, b2, fw1, fb1, fw2, fb2, pw, pb, out);
}